// round 14
// baseline (speedup 1.0000x reference)
#include <cuda_runtime.h>
#include <cuda_fp16.h>
#include <math.h>
#include <cstdint>

#define Bsz   2
#define Ssz   2048
#define INDIM 1024
#define EMB   1024
#define NH    16
#define HD    64
#define PADW  128

#define M1 (Bsz*Ssz)   /* 4096 */
#define N1 (3*EMB)     /* 3072 */

// ---------------------------------------------------------------------------
// Baseline-ISA PTX helpers (compute_103-legal)
// ---------------------------------------------------------------------------
__device__ __forceinline__ uint32_t smem_to_u32(const void* p) {
    uint32_t a;
    asm("{ .reg .u64 t; cvta.to.shared.u64 t, %1; cvt.u32.u64 %0, t; }" : "=r"(a) : "l"(p));
    return a;
}
#define CP_ASYNC16(saddr, gptr) \
    asm volatile("cp.async.cg.shared.global [%0], [%1], 16;" :: "r"(saddr), "l"(gptr))
#define CP_COMMIT() asm volatile("cp.async.commit_group;" ::: "memory")
#define CP_WAIT1()  asm volatile("cp.async.wait_group 1;" ::: "memory")
#define CP_WAIT0()  asm volatile("cp.async.wait_group 0;" ::: "memory")

__device__ __forceinline__ void ldm_x4(uint32_t* r, uint32_t addr) {
    asm volatile("ldmatrix.sync.aligned.m8n8.x4.shared.b16 {%0,%1,%2,%3}, [%4];"
        : "=r"(r[0]), "=r"(r[1]), "=r"(r[2]), "=r"(r[3]) : "r"(addr));
}
__device__ __forceinline__ void mma_fp16(float* d, const uint32_t* a, const uint32_t* b) {
    asm volatile("mma.sync.aligned.m16n8k16.row.col.f32.f16.f16.f32 "
        "{%0,%1,%2,%3}, {%4,%5,%6,%7}, {%8,%9}, {%0,%1,%2,%3};"
        : "+f"(d[0]), "+f"(d[1]), "+f"(d[2]), "+f"(d[3])
        : "r"(a[0]), "r"(a[1]), "r"(a[2]), "r"(a[3]), "r"(b[0]), "r"(b[1]));
}

// ---------------------------------------------------------------------------
// Scratch (static device globals) — all fp16
// ---------------------------------------------------------------------------
__device__ __half g_x16[M1*INDIM];
__device__ __half g_w16[N1*INDIM];
__device__ __half g_wo16[EMB*EMB];
__device__ __half g_av16[M1*EMB];
__device__ __half g_q16[Bsz*NH*Ssz*HD];
__device__ __half g_k16[Bsz*NH*Ssz*HD];
__device__ __half g_vt16[Bsz*NH*HD*Ssz];   // V transposed [b,h,d,s]

// ---------------------------------------------------------------------------
// Single fused fp32 -> fp16 conversion kernel (x | Wqkv | Wo)
// ---------------------------------------------------------------------------
#define NX  ((M1*INDIM)/4)
#define NW  ((N1*INDIM)/4)
#define NWO ((EMB*EMB)/4)

__global__ void conv_all(const float4* __restrict__ x,
                         const float4* __restrict__ w,
                         const float4* __restrict__ wo)
{
    int i = blockIdx.x * blockDim.x + threadIdx.x;
    const float4* src;
    __half2* dst;
    int j;
    if (i < NX)            { src = x;  dst = (__half2*)g_x16;  j = i; }
    else if (i < NX + NW)  { src = w;  dst = (__half2*)g_w16;  j = i - NX; }
    else if (i < NX + NW + NWO) { src = wo; dst = (__half2*)g_wo16; j = i - NX - NW; }
    else return;
    float4 f = src[j];
    dst[2*j]   = __floats2half2_rn(f.x, f.y);
    dst[2*j+1] = __floats2half2_rn(f.z, f.w);
}

// ---------------------------------------------------------------------------
// Single-fp16 HMMA GEMM: CTA 128x128, BK=32, 8 warps, 3-stage cp.async
// pipeline, one __syncthreads per chunk. 61440 B smem -> 3 CTAs/SM.
// ---------------------------------------------------------------------------
#define TILE_B 10240
#define STG_SZ (2 * TILE_B)
#define GEMM_SMEM (3 * STG_SZ)

__device__ __forceinline__ void load2_async(
    const __half* a, const __half* bw,
    int m0, int n0, int k0, uint32_t sb, int stg, int t)
{
    uint32_t base = sb + stg * STG_SZ;
    #pragma unroll
    for (int i = 0; i < 2; i++) {
        int c  = t + i * 256;
        int r  = c >> 2;
        int kc = c & 3;
        size_t goffA = (size_t)(m0 + r) * 1024 + k0 + kc * 8;
        size_t goffB = (size_t)(n0 + r) * 1024 + k0 + kc * 8;
        uint32_t soff = (uint32_t)(r * 80 + kc * 16);
        CP_ASYNC16(base + soff,          a  + goffA);
        CP_ASYNC16(base + TILE_B + soff, bw + goffB);
    }
}

__device__ __forceinline__ void gemm1_mainloop(
    const __half* __restrict__ a, const __half* __restrict__ bw,
    int m0, int n0, uint32_t sb, int t, float acc[4][4][4])
{
    const int lane = t & 31, wid = t >> 5;
    const int wm = (wid >> 2) * 64, wn = (wid & 3) * 32;

    #pragma unroll
    for (int x = 0; x < 4; x++)
        #pragma unroll
        for (int y = 0; y < 4; y++)
            #pragma unroll
            for (int e = 0; e < 4; e++)
                acc[x][y][e] = 0.f;

    load2_async(a, bw, m0, n0, 0,  sb, 0, t); CP_COMMIT();
    load2_async(a, bw, m0, n0, 32, sb, 1, t); CP_COMMIT();

    const int arow = wm + (lane & 15);
    const int akd  = (lane & 16) >> 1;
    const int nrow = wn + (lane & 7) + ((lane & 16) >> 1);
    const int bkd  = (lane & 8);

    for (int ch = 0; ch < 32; ch++) {
        if (ch < 31) CP_WAIT1(); else CP_WAIT0();
        __syncthreads();
        if (ch + 2 < 32) {
            load2_async(a, bw, m0, n0, (ch + 2) * 32, sb, (ch + 2) % 3, t);
            CP_COMMIT();
        }
        const uint32_t base = sb + (ch % 3) * STG_SZ;
        #pragma unroll
        for (int ks = 0; ks < 2; ks++) {
            const int kk = ks * 16;
            uint32_t af[4][4], bwf[2][4];
            #pragma unroll
            for (int mt = 0; mt < 4; mt++) {
                uint32_t off = (uint32_t)((arow + mt * 16) * 80 + (kk + akd) * 2);
                ldm_x4(af[mt], base + off);
            }
            #pragma unroll
            for (int g = 0; g < 2; g++) {
                uint32_t off = (uint32_t)((nrow + g * 16) * 80 + (kk + bkd) * 2);
                ldm_x4(bwf[g], base + TILE_B + off);
            }
            #pragma unroll
            for (int mt = 0; mt < 4; mt++)
                #pragma unroll
                for (int nt = 0; nt < 4; nt++) {
                    const uint32_t* b2 = &bwf[nt >> 1][(nt & 1) * 2];
                    mma_fp16(acc[mt][nt], af[mt], b2);
                }
        }
    }
}

// QKV projection: bias + padding mask, emit single fp16 q,k [b,h,s,d],
// v transposed [b,h,d,s]. 3 CTAs/SM (reg budget 85).
__global__ __launch_bounds__(256, 3) void qkv_mma(
    const float* __restrict__ bias, const int* __restrict__ pm)
{
    extern __shared__ __align__(16) char smem[];
    const uint32_t sb = smem_to_u32(smem);
    const int t = threadIdx.x, lane = t & 31, wid = t >> 5;
    const int wm = (wid >> 2) * 64, wn = (wid & 3) * 32;
    const int n0 = blockIdx.x * 128, m0 = blockIdx.y * 128;

    float acc[4][4][4];
    gemm1_mainloop(g_x16, g_w16, m0, n0, sb, t, acc);

    const int lr = lane >> 2, lc = (lane & 3) * 2;
    #pragma unroll
    for (int mt = 0; mt < 4; mt++) {
        #pragma unroll
        for (int half = 0; half < 2; half++) {
            const int m = m0 + wm + mt * 16 + lr + half * 8;
            const int msk = pm[m];
            const int bb = m >> 11, s = m & 2047;
            #pragma unroll
            for (int nt = 0; nt < 4; nt++) {
                #pragma unroll
                for (int e = 0; e < 2; e++) {
                    const int n = n0 + wn + nt * 8 + lc + e;
                    float val = msk ? 0.0f : (acc[mt][nt][half * 2 + e] + bias[n]);
                    __half v16 = __float2half_rn(val);
                    int h  = n / 192;
                    int cc = n - h * 192;
                    if (cc < HD)
                        g_q16[((bb * NH + h) * Ssz + s) * HD + cc] = v16;
                    else if (cc < 2*HD)
                        g_k16[((bb * NH + h) * Ssz + s) * HD + cc - HD] = v16;
                    else
                        g_vt16[((bb * NH + h) * HD + cc - 2*HD) * Ssz + s] = v16;
                }
            }
        }
    }
}

// Output projection: out = attn_vals @ Wo^T + bo. 3 CTAs/SM.
__global__ __launch_bounds__(256, 3) void out_mma(
    const float* __restrict__ bias, float* __restrict__ C)
{
    extern __shared__ __align__(16) char smem[];
    const uint32_t sb = smem_to_u32(smem);
    const int t = threadIdx.x, lane = t & 31, wid = t >> 5;
    const int wm = (wid >> 2) * 64, wn = (wid & 3) * 32;
    const int n0 = blockIdx.x * 128, m0 = blockIdx.y * 128;

    float acc[4][4][4];
    gemm1_mainloop(g_av16, g_wo16, m0, n0, sb, t, acc);

    const int lr = lane >> 2, lc = (lane & 3) * 2;
    #pragma unroll
    for (int mt = 0; mt < 4; mt++) {
        #pragma unroll
        for (int half = 0; half < 2; half++) {
            const int m = m0 + wm + mt * 16 + lr + half * 8;
            #pragma unroll
            for (int nt = 0; nt < 4; nt++) {
                const int n = n0 + wn + nt * 8 + lc;
                float2 o;
                o.x = acc[mt][nt][half * 2 + 0] + bias[n];
                o.y = acc[mt][nt][half * 2 + 1] + bias[n + 1];
                *reinterpret_cast<float2*>(C + (size_t)m * EMB + n) = o;
            }
        }
    }
}

// ---------------------------------------------------------------------------
// Banded attention, online softmax, single-fp16 QK and PV (validated R13).
// One block per (b,h,64-query tile), 256 threads, ~38 KB smem, 2 CTAs/SM.
// ---------------------------------------------------------------------------
#define ARS  144
#define OFF_Q   0
#define OFF_K   9216
#define OFF_V   18432
#define OFF_P   27648
#define OFF_MR  36864
#define OFF_SR  (OFF_MR + 256)
#define OFF_ALP (OFF_MR + 512)
#define OFF_ST  (OFF_MR + 768)
#define ATTN_SMEM (OFF_MR + 768 + 512)   /* 38144 */

__global__ __launch_bounds__(256, 2) void attn_kernel()
{
    extern __shared__ __align__(16) char smem[];
    const uint32_t sbase = smem_to_u32(smem);
    float* m_run = (float*)(smem + OFF_MR);
    float* s_run = (float*)(smem + OFF_SR);
    float* alphv = (float*)(smem + OFF_ALP);
    float* stats = (float*)(smem + OFF_ST);

    const int t = threadIdx.x, lane = t & 31, w = t >> 5;
    const int b  = blockIdx.y >> 4, h = blockIdx.y & 15;
    const int qs = blockIdx.x * 64;
    const int kb = qs - PADW;

    const size_t qkbase = (size_t)(b * NH + h) * Ssz * HD;
    const size_t vbase  = (size_t)(b * NH + h) * HD * Ssz;

    const int wm4 = (w >> 1) << 4;
    const int wnI = w & 1;
    const int wn  = wnI << 5;
    const int arow = wm4 + (lane & 15);
    const int akd  = (lane & 16) >> 1;
    const int nrow8 = (lane & 7) + ((lane & 16) >> 1);
    const int bkd  = (lane & 8);
    const int lr = lane >> 2, lc = (lane & 3) * 2;
    const int r0 = wm4 + lr;
    const float scale = 0.125f;

    if (t < 64) { m_run[t] = -1e30f; s_run[t] = 0.f; }
    #pragma unroll
    for (int i = 0; i < 2; i++) {
        int u = t + i * 256;
        int row = u >> 3;
        int c8  = (u & 7) * 8;
        *reinterpret_cast<uint4*>(smem + OFF_Q + row * ARS + c8 * 2) =
            *reinterpret_cast<const uint4*>(g_q16 + qkbase + (size_t)(qs + row) * HD + c8);
    }

    float acc2[4][4];
    #pragma unroll
    for (int nt = 0; nt < 4; nt++)
        #pragma unroll
        for (int e = 0; e < 4; e++) acc2[nt][e] = 0.f;

    for (int ch = 0; ch < 5; ch++) {
        __syncthreads();
        #pragma unroll
        for (int i = 0; i < 2; i++) {
            int u   = t + i * 256;
            int row = u >> 3;
            int c8  = (u & 7) * 8;
            uint32_t soff = (uint32_t)(row * ARS + c8 * 2);
            int j = kb + ch * 64 + row;
            uint4 kk4 = make_uint4(0,0,0,0);
            if (j >= 0 && j < Ssz)
                kk4 = *reinterpret_cast<const uint4*>(g_k16 + qkbase + (size_t)j * HD + c8);
            *reinterpret_cast<uint4*>(smem + OFF_K + soff) = kk4;
            int j0 = kb + ch * 64 + c8;
            uint4 vv4 = make_uint4(0,0,0,0);
            if (j0 >= 0 && j0 < Ssz)
                vv4 = *reinterpret_cast<const uint4*>(g_vt16 + vbase + (size_t)row * Ssz + j0);
            *reinterpret_cast<uint4*>(smem + OFF_V + soff) = vv4;
        }
        __syncthreads();

        float s[4][4];
        #pragma unroll
        for (int nt = 0; nt < 4; nt++)
            #pragma unroll
            for (int e = 0; e < 4; e++) s[nt][e] = 0.f;

        #pragma unroll
        for (int ks = 0; ks < 4; ks++) {
            const int kk = ks * 16;
            uint32_t q4[4], k4[2][4];
            ldm_x4(q4, sbase + OFF_Q + (uint32_t)(arow * ARS + (kk + akd) * 2));
            #pragma unroll
            for (int g = 0; g < 2; g++)
                ldm_x4(k4[g], sbase + OFF_K +
                       (uint32_t)((wn + nrow8 + g * 16) * ARS + (kk + bkd) * 2));
            #pragma unroll
            for (int nt = 0; nt < 4; nt++)
                mma_fp16(s[nt], q4, &k4[nt >> 1][(nt & 1) * 2]);
        }

        float mx0 = -1e30f, mx1 = -1e30f;
        #pragma unroll
        for (int nt = 0; nt < 4; nt++) {
            #pragma unroll
            for (int e = 0; e < 2; e++) {
                const int C = ch * 64 + wn + nt * 8 + lc + e;
                const int j = kb + C;
                const bool jv = (j >= 0) && (j < Ssz);
                if (!(jv && C >= r0 && C <= r0 + 256))          s[nt][e]     = -1e30f;
                if (!(jv && C >= r0 + 8 && C <= r0 + 8 + 256))  s[nt][2 + e] = -1e30f;
                mx0 = fmaxf(mx0, s[nt][e]);
                mx1 = fmaxf(mx1, s[nt][2 + e]);
            }
        }
        mx0 = fmaxf(mx0, __shfl_xor_sync(0xffffffffu, mx0, 1));
        mx0 = fmaxf(mx0, __shfl_xor_sync(0xffffffffu, mx0, 2));
        mx1 = fmaxf(mx1, __shfl_xor_sync(0xffffffffu, mx1, 1));
        mx1 = fmaxf(mx1, __shfl_xor_sync(0xffffffffu, mx1, 2));
        if ((lane & 3) == 0) {
            stats[r0 * 2 + wnI]       = mx0;
            stats[(r0 + 8) * 2 + wnI] = mx1;
        }
        __syncthreads();

        if (t < 64) {
            float mc = fmaxf(stats[t * 2], stats[t * 2 + 1]);
            float mo = m_run[t];
            float mn = fmaxf(mo, mc);
            float a  = __expf((mo - mn) * scale);
            alphv[t] = a;
            m_run[t] = mn;
            s_run[t] *= a;
        }
        __syncthreads();

        {
            const float a0 = alphv[r0], a1 = alphv[r0 + 8];
            #pragma unroll
            for (int nt = 0; nt < 4; nt++) {
                acc2[nt][0] *= a0; acc2[nt][1] *= a0;
                acc2[nt][2] *= a1; acc2[nt][3] *= a1;
            }
            const float mn0 = m_run[r0] * scale, mn1 = m_run[r0 + 8] * scale;
            float sum0 = 0.f, sum1 = 0.f;
            #pragma unroll
            for (int nt = 0; nt < 4; nt++) {
                const int colc = wn + nt * 8 + lc;
                float e0a = __expf(s[nt][0] * scale - mn0);
                float e0b = __expf(s[nt][1] * scale - mn0);
                float e1a = __expf(s[nt][2] * scale - mn1);
                float e1b = __expf(s[nt][3] * scale - mn1);
                sum0 += e0a + e0b;
                sum1 += e1a + e1b;
                *reinterpret_cast<__half2*>(smem + OFF_P + r0 * ARS + colc * 2) =
                    __floats2half2_rn(e0a, e0b);
                *reinterpret_cast<__half2*>(smem + OFF_P + (r0 + 8) * ARS + colc * 2) =
                    __floats2half2_rn(e1a, e1b);
            }
            sum0 += __shfl_xor_sync(0xffffffffu, sum0, 1);
            sum0 += __shfl_xor_sync(0xffffffffu, sum0, 2);
            sum1 += __shfl_xor_sync(0xffffffffu, sum1, 1);
            sum1 += __shfl_xor_sync(0xffffffffu, sum1, 2);
            if ((lane & 3) == 0) {
                atomicAdd(&s_run[r0], sum0);
                atomicAdd(&s_run[r0 + 8], sum1);
            }
        }
        __syncthreads();

        #pragma unroll
        for (int ks = 0; ks < 4; ks++) {
            const int kk = ks * 16;
            uint32_t p4[4], v4[2][4];
            ldm_x4(p4, sbase + OFF_P + (uint32_t)(arow * ARS + (kk + akd) * 2));
            #pragma unroll
            for (int g = 0; g < 2; g++)
                ldm_x4(v4[g], sbase + OFF_V +
                       (uint32_t)((wn + nrow8 + g * 16) * ARS + (kk + bkd) * 2));
            #pragma unroll
            for (int nt = 0; nt < 4; nt++)
                mma_fp16(acc2[nt], p4, &v4[nt >> 1][(nt & 1) * 2]);
        }
    }
    __syncthreads();

    #pragma unroll
    for (int half = 0; half < 2; half++) {
        const int r  = r0 + half * 8;
        const float is = 1.0f / s_run[r];
        const size_t rowbase = (size_t)(b * Ssz + qs + r) * EMB + h * HD;
        #pragma unroll
        for (int nt = 0; nt < 4; nt++) {
            const int d = wn + nt * 8 + lc;
            float v0 = acc2[nt][half * 2 + 0] * is;
            float v1 = acc2[nt][half * 2 + 1] * is;
            *reinterpret_cast<__half2*>(g_av16 + rowbase + d) = __floats2half2_rn(v0, v1);
        }
    }
}

// ---------------------------------------------------------------------------
extern "C" void kernel_launch(void* const* d_in, const int* in_sizes, int n_in,
                              void* d_out, int out_size)
{
    const float* x    = (const float*)d_in[0];
    const int*   pm   = (const int*)  d_in[1];
    const float* Wqkv = (const float*)d_in[2];
    const float* bqkv = (const float*)d_in[3];
    const float* Wo   = (const float*)d_in[4];
    const float* bo   = (const float*)d_in[5];
    float* out = (float*)d_out;

    cudaFuncSetAttribute(attn_kernel,
                         cudaFuncAttributeMaxDynamicSharedMemorySize, ATTN_SMEM);
    cudaFuncSetAttribute(qkv_mma,
                         cudaFuncAttributeMaxDynamicSharedMemorySize, GEMM_SMEM);
    cudaFuncSetAttribute(out_mma,
                         cudaFuncAttributeMaxDynamicSharedMemorySize, GEMM_SMEM);

    conv_all<<<(NX + NW + NWO + 255)/256, 256>>>(
        (const float4*)x, (const float4*)Wqkv, (const float4*)Wo);

    qkv_mma<<<dim3(N1/128, M1/128), 256, GEMM_SMEM>>>(bqkv, pm);

    attn_kernel<<<dim3(Ssz/64, Bsz*NH), 256, ATTN_SMEM>>>();

    out_mma<<<dim3(EMB/128, M1/128), 256, GEMM_SMEM>>>(bo, out);
}

// round 15
// speedup vs baseline: 1.2142x; 1.2142x over previous
#include <cuda_runtime.h>
#include <cuda_fp16.h>
#include <math.h>
#include <cstdint>

#define Bsz   2
#define Ssz   2048
#define INDIM 1024
#define EMB   1024
#define NH    16
#define HD    64
#define PADW  128

#define M1 (Bsz*Ssz)   /* 4096 */
#define N1 (3*EMB)     /* 3072 */

// ---------------------------------------------------------------------------
// Baseline-ISA PTX helpers (compute_103-legal)
// ---------------------------------------------------------------------------
__device__ __forceinline__ uint32_t smem_to_u32(const void* p) {
    uint32_t a;
    asm("{ .reg .u64 t; cvta.to.shared.u64 t, %1; cvt.u32.u64 %0, t; }" : "=r"(a) : "l"(p));
    return a;
}
#define CP_ASYNC16(saddr, gptr) \
    asm volatile("cp.async.cg.shared.global [%0], [%1], 16;" :: "r"(saddr), "l"(gptr))
#define CP_COMMIT() asm volatile("cp.async.commit_group;" ::: "memory")
#define CP_WAIT0()  asm volatile("cp.async.wait_group 0;" ::: "memory")

__device__ __forceinline__ void ldm_x4(uint32_t* r, uint32_t addr) {
    asm volatile("ldmatrix.sync.aligned.m8n8.x4.shared.b16 {%0,%1,%2,%3}, [%4];"
        : "=r"(r[0]), "=r"(r[1]), "=r"(r[2]), "=r"(r[3]) : "r"(addr));
}
__device__ __forceinline__ void mma_fp16(float* d, const uint32_t* a, const uint32_t* b) {
    asm volatile("mma.sync.aligned.m16n8k16.row.col.f32.f16.f16.f32 "
        "{%0,%1,%2,%3}, {%4,%5,%6,%7}, {%8,%9}, {%0,%1,%2,%3};"
        : "+f"(d[0]), "+f"(d[1]), "+f"(d[2]), "+f"(d[3])
        : "r"(a[0]), "r"(a[1]), "r"(a[2]), "r"(a[3]), "r"(b[0]), "r"(b[1]));
}

// ---------------------------------------------------------------------------
// Scratch (static device globals) — all fp16
// ---------------------------------------------------------------------------
__device__ __half g_x16[M1*INDIM];
__device__ __half g_w16[N1*INDIM];
__device__ __half g_wo16[EMB*EMB];
__device__ __half g_av16[M1*EMB];
__device__ __half g_q16[Bsz*NH*Ssz*HD];
__device__ __half g_k16[Bsz*NH*Ssz*HD];
__device__ __half g_vt16[Bsz*NH*HD*Ssz];   // V transposed [b,h,d,s]

// ---------------------------------------------------------------------------
// Single fused fp32 -> fp16 conversion kernel (x | Wqkv | Wo)
// ---------------------------------------------------------------------------
#define NX  ((M1*INDIM)/4)
#define NW  ((N1*INDIM)/4)
#define NWO ((EMB*EMB)/4)

__global__ void conv_all(const float4* __restrict__ x,
                         const float4* __restrict__ w,
                         const float4* __restrict__ wo)
{
    int i = blockIdx.x * blockDim.x + threadIdx.x;
    const float4* src;
    __half2* dst;
    int j;
    if (i < NX)            { src = x;  dst = (__half2*)g_x16;  j = i; }
    else if (i < NX + NW)  { src = w;  dst = (__half2*)g_w16;  j = i - NX; }
    else if (i < NX + NW + NWO) { src = wo; dst = (__half2*)g_wo16; j = i - NX - NW; }
    else return;
    float4 f = src[j];
    dst[2*j]   = __floats2half2_rn(f.x, f.y);
    dst[2*j+1] = __floats2half2_rn(f.z, f.w);
}

// ---------------------------------------------------------------------------
// Single-fp16 HMMA GEMM: CTA 128x128, BK=64, 8 warps (64x32 warp tile),
// 2-stage double buffer, ONE __syncthreads per chunk (16 chunks).
// Rows padded to 72 halves (144 B, conflict-free). 73728 B smem -> 2 CTAs/SM.
// ---------------------------------------------------------------------------
#define GRS    144                  /* bytes per smem row */
#define TILE_B (128 * GRS)          /* 18432 */
#define STG_SZ (2 * TILE_B)         /* 36864 */
#define GEMM_SMEM (2 * STG_SZ)      /* 73728 */

__device__ __forceinline__ void load2_async(
    const __half* a, const __half* bw,
    int m0, int n0, int k0, uint32_t sb, int stg, int t)
{
    uint32_t base = sb + stg * STG_SZ;
    #pragma unroll
    for (int i = 0; i < 4; i++) {
        int c  = t + i * 256;        // 0..1023 : 16B units of one tile
        int r  = c >> 3;             // row 0..127
        int kc = c & 7;              // 16B unit within 128B of row data
        size_t goffA = (size_t)(m0 + r) * 1024 + k0 + kc * 8;
        size_t goffB = (size_t)(n0 + r) * 1024 + k0 + kc * 8;
        uint32_t soff = (uint32_t)(r * GRS + kc * 16);
        CP_ASYNC16(base + soff,          a  + goffA);
        CP_ASYNC16(base + TILE_B + soff, bw + goffB);
    }
}

__device__ __forceinline__ void gemm1_mainloop(
    const __half* __restrict__ a, const __half* __restrict__ bw,
    int m0, int n0, uint32_t sb, int t, float acc[4][4][4])
{
    const int lane = t & 31, wid = t >> 5;
    const int wm = (wid >> 2) * 64, wn = (wid & 3) * 32;

    #pragma unroll
    for (int x = 0; x < 4; x++)
        #pragma unroll
        for (int y = 0; y < 4; y++)
            #pragma unroll
            for (int e = 0; e < 4; e++)
                acc[x][y][e] = 0.f;

    load2_async(a, bw, m0, n0, 0, sb, 0, t);
    CP_COMMIT();

    const int arow = wm + (lane & 15);
    const int akd  = (lane & 16) >> 1;
    const int nrow = wn + (lane & 7) + ((lane & 16) >> 1);
    const int bkd  = (lane & 8);

    for (int ch = 0; ch < 16; ch++) {
        CP_WAIT0();            // chunk ch's tiles are in smem (this thread)
        __syncthreads();       // publish to all; prior readers of next buf done
        if (ch + 1 < 16) {
            load2_async(a, bw, m0, n0, (ch + 1) * 64, sb, (ch + 1) & 1, t);
            CP_COMMIT();       // overlaps with the compute below
        }
        const uint32_t base = sb + (ch & 1) * STG_SZ;
        #pragma unroll
        for (int ks = 0; ks < 4; ks++) {
            const int kk = ks * 16;
            uint32_t af[4][4], bwf[2][4];
            #pragma unroll
            for (int mt = 0; mt < 4; mt++) {
                uint32_t off = (uint32_t)((arow + mt * 16) * GRS + (kk + akd) * 2);
                ldm_x4(af[mt], base + off);
            }
            #pragma unroll
            for (int g = 0; g < 2; g++) {
                uint32_t off = (uint32_t)((nrow + g * 16) * GRS + (kk + bkd) * 2);
                ldm_x4(bwf[g], base + TILE_B + off);
            }
            #pragma unroll
            for (int mt = 0; mt < 4; mt++)
                #pragma unroll
                for (int nt = 0; nt < 4; nt++) {
                    const uint32_t* b2 = &bwf[nt >> 1][(nt & 1) * 2];
                    mma_fp16(acc[mt][nt], af[mt], b2);
                }
        }
    }
}

// QKV projection: bias + padding mask, emit single fp16 q,k [b,h,s,d],
// v transposed [b,h,d,s].
__global__ __launch_bounds__(256) void qkv_mma(
    const float* __restrict__ bias, const int* __restrict__ pm)
{
    extern __shared__ __align__(16) char smem[];
    const uint32_t sb = smem_to_u32(smem);
    const int t = threadIdx.x, lane = t & 31, wid = t >> 5;
    const int wm = (wid >> 2) * 64, wn = (wid & 3) * 32;
    const int n0 = blockIdx.x * 128, m0 = blockIdx.y * 128;

    float acc[4][4][4];
    gemm1_mainloop(g_x16, g_w16, m0, n0, sb, t, acc);

    const int lr = lane >> 2, lc = (lane & 3) * 2;
    #pragma unroll
    for (int mt = 0; mt < 4; mt++) {
        #pragma unroll
        for (int half = 0; half < 2; half++) {
            const int m = m0 + wm + mt * 16 + lr + half * 8;
            const int msk = pm[m];
            const int bb = m >> 11, s = m & 2047;
            #pragma unroll
            for (int nt = 0; nt < 4; nt++) {
                #pragma unroll
                for (int e = 0; e < 2; e++) {
                    const int n = n0 + wn + nt * 8 + lc + e;
                    float val = msk ? 0.0f : (acc[mt][nt][half * 2 + e] + bias[n]);
                    __half v16 = __float2half_rn(val);
                    int h  = n / 192;
                    int cc = n - h * 192;
                    if (cc < HD)
                        g_q16[((bb * NH + h) * Ssz + s) * HD + cc] = v16;
                    else if (cc < 2*HD)
                        g_k16[((bb * NH + h) * Ssz + s) * HD + cc - HD] = v16;
                    else
                        g_vt16[((bb * NH + h) * HD + cc - 2*HD) * Ssz + s] = v16;
                }
            }
        }
    }
}

// Output projection: out = attn_vals @ Wo^T + bo
__global__ __launch_bounds__(256) void out_mma(
    const float* __restrict__ bias, float* __restrict__ C)
{
    extern __shared__ __align__(16) char smem[];
    const uint32_t sb = smem_to_u32(smem);
    const int t = threadIdx.x, lane = t & 31, wid = t >> 5;
    const int wm = (wid >> 2) * 64, wn = (wid & 3) * 32;
    const int n0 = blockIdx.x * 128, m0 = blockIdx.y * 128;

    float acc[4][4][4];
    gemm1_mainloop(g_av16, g_wo16, m0, n0, sb, t, acc);

    const int lr = lane >> 2, lc = (lane & 3) * 2;
    #pragma unroll
    for (int mt = 0; mt < 4; mt++) {
        #pragma unroll
        for (int half = 0; half < 2; half++) {
            const int m = m0 + wm + mt * 16 + lr + half * 8;
            #pragma unroll
            for (int nt = 0; nt < 4; nt++) {
                const int n = n0 + wn + nt * 8 + lc;
                float2 o;
                o.x = acc[mt][nt][half * 2 + 0] + bias[n];
                o.y = acc[mt][nt][half * 2 + 1] + bias[n + 1];
                *reinterpret_cast<float2*>(C + (size_t)m * EMB + n) = o;
            }
        }
    }
}

// ---------------------------------------------------------------------------
// Banded attention, online softmax, single-fp16 QK and PV (validated R13,
// unchanged). One block per (b,h,64-query tile), 256 threads, 2 CTAs/SM.
// ---------------------------------------------------------------------------
#define ARS  144
#define OFF_Q   0
#define OFF_K   9216
#define OFF_V   18432
#define OFF_P   27648
#define OFF_MR  36864
#define OFF_SR  (OFF_MR + 256)
#define OFF_ALP (OFF_MR + 512)
#define OFF_ST  (OFF_MR + 768)
#define ATTN_SMEM (OFF_MR + 768 + 512)   /* 38144 */

__global__ __launch_bounds__(256, 2) void attn_kernel()
{
    extern __shared__ __align__(16) char smem[];
    const uint32_t sbase = smem_to_u32(smem);
    float* m_run = (float*)(smem + OFF_MR);
    float* s_run = (float*)(smem + OFF_SR);
    float* alphv = (float*)(smem + OFF_ALP);
    float* stats = (float*)(smem + OFF_ST);

    const int t = threadIdx.x, lane = t & 31, w = t >> 5;
    const int b  = blockIdx.y >> 4, h = blockIdx.y & 15;
    const int qs = blockIdx.x * 64;
    const int kb = qs - PADW;

    const size_t qkbase = (size_t)(b * NH + h) * Ssz * HD;
    const size_t vbase  = (size_t)(b * NH + h) * HD * Ssz;

    const int wm4 = (w >> 1) << 4;
    const int wnI = w & 1;
    const int wn  = wnI << 5;
    const int arow = wm4 + (lane & 15);
    const int akd  = (lane & 16) >> 1;
    const int nrow8 = (lane & 7) + ((lane & 16) >> 1);
    const int bkd  = (lane & 8);
    const int lr = lane >> 2, lc = (lane & 3) * 2;
    const int r0 = wm4 + lr;
    const float scale = 0.125f;

    if (t < 64) { m_run[t] = -1e30f; s_run[t] = 0.f; }
    #pragma unroll
    for (int i = 0; i < 2; i++) {
        int u = t + i * 256;
        int row = u >> 3;
        int c8  = (u & 7) * 8;
        *reinterpret_cast<uint4*>(smem + OFF_Q + row * ARS + c8 * 2) =
            *reinterpret_cast<const uint4*>(g_q16 + qkbase + (size_t)(qs + row) * HD + c8);
    }

    float acc2[4][4];
    #pragma unroll
    for (int nt = 0; nt < 4; nt++)
        #pragma unroll
        for (int e = 0; e < 4; e++) acc2[nt][e] = 0.f;

    for (int ch = 0; ch < 5; ch++) {
        __syncthreads();
        #pragma unroll
        for (int i = 0; i < 2; i++) {
            int u   = t + i * 256;
            int row = u >> 3;
            int c8  = (u & 7) * 8;
            uint32_t soff = (uint32_t)(row * ARS + c8 * 2);
            int j = kb + ch * 64 + row;
            uint4 kk4 = make_uint4(0,0,0,0);
            if (j >= 0 && j < Ssz)
                kk4 = *reinterpret_cast<const uint4*>(g_k16 + qkbase + (size_t)j * HD + c8);
            *reinterpret_cast<uint4*>(smem + OFF_K + soff) = kk4;
            int j0 = kb + ch * 64 + c8;
            uint4 vv4 = make_uint4(0,0,0,0);
            if (j0 >= 0 && j0 < Ssz)
                vv4 = *reinterpret_cast<const uint4*>(g_vt16 + vbase + (size_t)row * Ssz + j0);
            *reinterpret_cast<uint4*>(smem + OFF_V + soff) = vv4;
        }
        __syncthreads();

        float s[4][4];
        #pragma unroll
        for (int nt = 0; nt < 4; nt++)
            #pragma unroll
            for (int e = 0; e < 4; e++) s[nt][e] = 0.f;

        #pragma unroll
        for (int ks = 0; ks < 4; ks++) {
            const int kk = ks * 16;
            uint32_t q4[4], k4[2][4];
            ldm_x4(q4, sbase + OFF_Q + (uint32_t)(arow * ARS + (kk + akd) * 2));
            #pragma unroll
            for (int g = 0; g < 2; g++)
                ldm_x4(k4[g], sbase + OFF_K +
                       (uint32_t)((wn + nrow8 + g * 16) * ARS + (kk + bkd) * 2));
            #pragma unroll
            for (int nt = 0; nt < 4; nt++)
                mma_fp16(s[nt], q4, &k4[nt >> 1][(nt & 1) * 2]);
        }

        float mx0 = -1e30f, mx1 = -1e30f;
        #pragma unroll
        for (int nt = 0; nt < 4; nt++) {
            #pragma unroll
            for (int e = 0; e < 2; e++) {
                const int C = ch * 64 + wn + nt * 8 + lc + e;
                const int j = kb + C;
                const bool jv = (j >= 0) && (j < Ssz);
                if (!(jv && C >= r0 && C <= r0 + 256))          s[nt][e]     = -1e30f;
                if (!(jv && C >= r0 + 8 && C <= r0 + 8 + 256))  s[nt][2 + e] = -1e30f;
                mx0 = fmaxf(mx0, s[nt][e]);
                mx1 = fmaxf(mx1, s[nt][2 + e]);
            }
        }
        mx0 = fmaxf(mx0, __shfl_xor_sync(0xffffffffu, mx0, 1));
        mx0 = fmaxf(mx0, __shfl_xor_sync(0xffffffffu, mx0, 2));
        mx1 = fmaxf(mx1, __shfl_xor_sync(0xffffffffu, mx1, 1));
        mx1 = fmaxf(mx1, __shfl_xor_sync(0xffffffffu, mx1, 2));
        if ((lane & 3) == 0) {
            stats[r0 * 2 + wnI]       = mx0;
            stats[(r0 + 8) * 2 + wnI] = mx1;
        }
        __syncthreads();

        if (t < 64) {
            float mc = fmaxf(stats[t * 2], stats[t * 2 + 1]);
            float mo = m_run[t];
            float mn = fmaxf(mo, mc);
            float a  = __expf((mo - mn) * scale);
            alphv[t] = a;
            m_run[t] = mn;
            s_run[t] *= a;
        }
        __syncthreads();

        {
            const float a0 = alphv[r0], a1 = alphv[r0 + 8];
            #pragma unroll
            for (int nt = 0; nt < 4; nt++) {
                acc2[nt][0] *= a0; acc2[nt][1] *= a0;
                acc2[nt][2] *= a1; acc2[nt][3] *= a1;
            }
            const float mn0 = m_run[r0] * scale, mn1 = m_run[r0 + 8] * scale;
            float sum0 = 0.f, sum1 = 0.f;
            #pragma unroll
            for (int nt = 0; nt < 4; nt++) {
                const int colc = wn + nt * 8 + lc;
                float e0a = __expf(s[nt][0] * scale - mn0);
                float e0b = __expf(s[nt][1] * scale - mn0);
                float e1a = __expf(s[nt][2] * scale - mn1);
                float e1b = __expf(s[nt][3] * scale - mn1);
                sum0 += e0a + e0b;
                sum1 += e1a + e1b;
                *reinterpret_cast<__half2*>(smem + OFF_P + r0 * ARS + colc * 2) =
                    __floats2half2_rn(e0a, e0b);
                *reinterpret_cast<__half2*>(smem + OFF_P + (r0 + 8) * ARS + colc * 2) =
                    __floats2half2_rn(e1a, e1b);
            }
            sum0 += __shfl_xor_sync(0xffffffffu, sum0, 1);
            sum0 += __shfl_xor_sync(0xffffffffu, sum0, 2);
            sum1 += __shfl_xor_sync(0xffffffffu, sum1, 1);
            sum1 += __shfl_xor_sync(0xffffffffu, sum1, 2);
            if ((lane & 3) == 0) {
                atomicAdd(&s_run[r0], sum0);
                atomicAdd(&s_run[r0 + 8], sum1);
            }
        }
        __syncthreads();

        #pragma unroll
        for (int ks = 0; ks < 4; ks++) {
            const int kk = ks * 16;
            uint32_t p4[4], v4[2][4];
            ldm_x4(p4, sbase + OFF_P + (uint32_t)(arow * ARS + (kk + akd) * 2));
            #pragma unroll
            for (int g = 0; g < 2; g++)
                ldm_x4(v4[g], sbase + OFF_V +
                       (uint32_t)((wn + nrow8 + g * 16) * ARS + (kk + bkd) * 2));
            #pragma unroll
            for (int nt = 0; nt < 4; nt++)
                mma_fp16(acc2[nt], p4, &v4[nt >> 1][(nt & 1) * 2]);
        }
    }
    __syncthreads();

    #pragma unroll
    for (int half = 0; half < 2; half++) {
        const int r  = r0 + half * 8;
        const float is = 1.0f / s_run[r];
        const size_t rowbase = (size_t)(b * Ssz + qs + r) * EMB + h * HD;
        #pragma unroll
        for (int nt = 0; nt < 4; nt++) {
            const int d = wn + nt * 8 + lc;
            float v0 = acc2[nt][half * 2 + 0] * is;
            float v1 = acc2[nt][half * 2 + 1] * is;
            *reinterpret_cast<__half2*>(g_av16 + rowbase + d) = __floats2half2_rn(v0, v1);
        }
    }
}

// ---------------------------------------------------------------------------
extern "C" void kernel_launch(void* const* d_in, const int* in_sizes, int n_in,
                              void* d_out, int out_size)
{
    const float* x    = (const float*)d_in[0];
    const int*   pm   = (const int*)  d_in[1];
    const float* Wqkv = (const float*)d_in[2];
    const float* bqkv = (const float*)d_in[3];
    const float* Wo   = (const float*)d_in[4];
    const float* bo   = (const float*)d_in[5];
    float* out = (float*)d_out;

    cudaFuncSetAttribute(attn_kernel,
                         cudaFuncAttributeMaxDynamicSharedMemorySize, ATTN_SMEM);
    cudaFuncSetAttribute(qkv_mma,
                         cudaFuncAttributeMaxDynamicSharedMemorySize, GEMM_SMEM);
    cudaFuncSetAttribute(out_mma,
                         cudaFuncAttributeMaxDynamicSharedMemorySize, GEMM_SMEM);

    conv_all<<<(NX + NW + NWO + 255)/256, 256>>>(
        (const float4*)x, (const float4*)Wqkv, (const float4*)Wo);

    qkv_mma<<<dim3(N1/128, M1/128), 256, GEMM_SMEM>>>(bqkv, pm);

    attn_kernel<<<dim3(Ssz/64, Bsz*NH), 256, ATTN_SMEM>>>();

    out_mma<<<dim3(EMB/128, M1/128), 256, GEMM_SMEM>>>(bo, out);
}